// round 7
// baseline (speedup 1.0000x reference)
#include <cuda_runtime.h>
#include <math.h>

#define NB 16
#define TT 12
#define AL 0.2f

__global__ __launch_bounds__(256) void gat_one(
    const float* __restrict__ inp,   // [NB,TT,64,64]
    const float* __restrict__ W,     // [64,64]
    const float* __restrict__ a,     // [128]
    float* __restrict__ out_elu,     // [NB,TT,64,64]
    float* __restrict__ out_att,     // [NB,TT,64,64]
    int write_att)
{
    __shared__ __align__(16) float s_WA[128];   // ti<6: WA1[64]; ti>=6: WAlo|WAhi
    __shared__ __align__(16) float s_cs[128];   // ti<6 own half colsums
    __shared__ __align__(16) float s_g [256];   // g1[64] or g2a[64]|pad|g2b[64]
    __shared__ __align__(16) float s_SW[128];   // ti<6: SW_lo|SW_hi
    __shared__ __align__(16) float s_p0[32], s_p1[32];
    __shared__ __align__(16) float s_att[32];
    __shared__ __align__(16) float s_wc[64], s_q[64];

    const int t   = threadIdx.x;
    const int bid = blockIdx.x, pair = bid >> 1, vb = bid & 1;
    const int n = pair / TT, ti = pair - n * TT;
    const bool first = (ti < 6);
    const int sl = first ? (2 * ti + vb) : (2 * (ti - 6) + vb);
    const float* src = inp + (size_t)(n * TT + sl) * 4096;
    const float* own = inp + (size_t)pair * 4096;

    const int warp = t >> 5, ln = t & 31;
    const int rq = ln >> 2, q = ln & 3;          // 4 lanes per row

    // ---- Stage A: WA row-dots from global W (8 warps x 8 rows) ----
    {
        const int k = warp * 8 + rq;
        const float4* W4  = (const float4*)W;    // row k at W4[k*16]
        const float4* Al4 = (const float4*)a;
        const float4* Ah4 = (const float4*)(a + 64);
        float lo = 0.f, hi = 0.f;
#pragma unroll
        for (int i = 0; i < 4; i++) {
            const float4 wv = W4[k * 16 + q * 4 + i];
            const float4 al = Al4[q * 4 + i];
            const float4 ah = Ah4[q * 4 + i];
            lo += wv.x * al.x + wv.y * al.y + wv.z * al.z + wv.w * al.w;
            hi += wv.x * ah.x + wv.y * ah.y + wv.z * ah.z + wv.w * ah.w;
        }
#pragma unroll
        for (int o = 1; o <= 2; o <<= 1) {
            lo += __shfl_xor_sync(0xffffffffu, lo, o);
            hi += __shfl_xor_sync(0xffffffffu, hi, o);
        }
        if (q == 0) {
            if (first) s_WA[k] = lo + hi;
            else       { s_WA[k] = lo; s_WA[64 + k] = hi; }
        }
    }
    // ---- Stage A2: (ti<6) own half colsums, coalesced direct from global ----
    if (first && t < 128) {
        const int hb = t >> 6, k = t & 63;
        const float* p = own + hb * 2048 + k;
        float c0 = 0.f, c1 = 0.f, c2 = 0.f, c3 = 0.f;
#pragma unroll
        for (int w = 0; w < 32; w += 4) {
            c0 += p[w * 64];
            c1 += p[(w + 1) * 64];
            c2 += p[(w + 2) * 64];
            c3 += p[(w + 3) * 64];
        }
        s_cs[t] = (c0 + c1) + (c2 + c3);
    }
    __syncthreads();

    // ---- Stage B: g row-dots from global src (8 warps x 8 rows) ----
    {
        const int u = warp * 8 + rq;
        const float4* S4 = (const float4*)src;
        if (first) {
            float g = 0.f;
#pragma unroll
            for (int i = 0; i < 4; i++) {
                const float4 sv = S4[u * 16 + q * 4 + i];
                const int j = q * 16 + i * 4;
                g += sv.x * s_WA[j] + sv.y * s_WA[j + 1]
                   + sv.z * s_WA[j + 2] + sv.w * s_WA[j + 3];
            }
#pragma unroll
            for (int o = 1; o <= 2; o <<= 1) g += __shfl_xor_sync(0xffffffffu, g, o);
            if (q == 0) s_g[u] = g;
        } else {
            float ga = 0.f, gb = 0.f;
#pragma unroll
            for (int i = 0; i < 4; i++) {
                const float4 sv = S4[u * 16 + q * 4 + i];
                const int j = q * 16 + i * 4;
                ga += sv.x * s_WA[j] + sv.y * s_WA[j + 1]
                    + sv.z * s_WA[j + 2] + sv.w * s_WA[j + 3];
                gb += sv.x * s_WA[64 + j] + sv.y * s_WA[64 + j + 1]
                    + sv.z * s_WA[64 + j + 2] + sv.w * s_WA[64 + j + 3];
            }
#pragma unroll
            for (int o = 1; o <= 2; o <<= 1) {
                ga += __shfl_xor_sync(0xffffffffu, ga, o);
                gb += __shfl_xor_sync(0xffffffffu, gb, o);
            }
            if (q == 0) { s_g[u] = ga; s_g[128 + u] = gb; }
        }
    }
    // ---- Stage B2: (ti<6) SW column-dots from global W ----
    if (first && t < 128) {
        const int c = t >> 6, j = t & 63;
        const float* cs = s_cs + c * 64;
        float s0 = 0.f, s1 = 0.f;
#pragma unroll
        for (int k = 0; k < 64; k += 2) {
            s0 = fmaf(cs[k],     W[k * 64 + j],       s0);
            s1 = fmaf(cs[k + 1], W[(k + 1) * 64 + j], s1);
        }
        s_SW[c * 64 + j] = s0 + s1;
    }
    __syncthreads();

    if (first) {
        // ---- Stage C: closed-form softmax (2 candidates per row) ----
        if (t < 32) {
            float e0 = s_g[2 * t], e1 = s_g[2 * t + 1];
            e0 = (e0 > 0.f) ? e0 : AL * e0;
            e1 = (e1 > 0.f) ? e1 : AL * e1;
            const float m = fmaxf(e0, e1);
            const float p0 = __expf(e0 - m), p1 = __expf(e1 - m);
            const float inv = 1.f / (32.f * (p0 + p1));
            s_p0[t] = p0 * inv;
            s_p1[t] = p1 * inv;
        }
        __syncthreads();

        // ---- Stage D: outputs (32 rows x 64 cols) ----
        float4* oe4 = (float4*)(out_elu + (size_t)pair * 4096 + vb * 2048);
        float4* oa4 = (float4*)(out_att + (size_t)pair * 4096 + vb * 2048);
        const float4* Qlo = (const float4*)s_SW;
        const float4* Qhi = (const float4*)(s_SW + 64);
#pragma unroll
        for (int i = 0; i < 2; i++) {
            const int idx4 = t + i * 256;            // [0,512)
            const int r = idx4 >> 4, w4 = idx4 & 15;
            const float a0 = s_p0[r], a1 = s_p1[r];
            const float4 q0 = Qlo[w4], q1 = Qhi[w4];
            float4 rr;
            rr.x = fmaf(a0, q0.x, a1 * q1.x);
            rr.y = fmaf(a0, q0.y, a1 * q1.y);
            rr.z = fmaf(a0, q0.z, a1 * q1.z);
            rr.w = fmaf(a0, q0.w, a1 * q1.w);
            rr.x = (rr.x > 0.f) ? rr.x : (__expf(rr.x) - 1.f);
            rr.y = (rr.y > 0.f) ? rr.y : (__expf(rr.y) - 1.f);
            rr.z = (rr.z > 0.f) ? rr.z : (__expf(rr.z) - 1.f);
            rr.w = (rr.w > 0.f) ? rr.w : (__expf(rr.w) - 1.f);
            oe4[idx4] = rr;
            if (write_att) {
                const float av = (w4 < 8) ? a0 : a1;
                oa4[idx4] = make_float4(av, av, av, av);
            }
        }
    } else {
        // ---- Stage C: 32-wide softmax (warp 0) ----
        if (t < 32) {
            float e = s_g[2 * t] + s_g[128 + 2 * t + 1];
            e = (e > 0.f) ? e : AL * e;
            float m = e;
#pragma unroll
            for (int o = 16; o; o >>= 1) m = fmaxf(m, __shfl_xor_sync(0xffffffffu, m, o));
            const float p = __expf(e - m);
            float ss = p;
#pragma unroll
            for (int o = 16; o; o >>= 1) ss += __shfl_xor_sync(0xffffffffu, ss, o);
            s_att[t] = p / (2.f * ss);
        }
        __syncthreads();

        // ---- Stage D: weighted colsum of own slab, coalesced from global ----
        if (t < 64) {
            const int k = t;
            float s0 = 0.f, s1 = 0.f;
#pragma unroll
            for (int w = 0; w < 64; w += 2) {
                s0 = fmaf(s_att[w & 31],       own[w * 64 + k],       s0);
                s1 = fmaf(s_att[(w + 1) & 31], own[(w + 1) * 64 + k], s1);
            }
            s_wc[k] = s0 + s1;
        }
        __syncthreads();

        // ---- Stage E: q[j] = wc . W[:,j], fold ELU ----
        if (t < 64) {
            const int j = t;
            float s0 = 0.f, s1 = 0.f;
#pragma unroll
            for (int k = 0; k < 64; k += 2) {
                s0 = fmaf(s_wc[k],     W[k * 64 + j],       s0);
                s1 = fmaf(s_wc[k + 1], W[(k + 1) * 64 + j], s1);
            }
            const float qv = s0 + s1;
            s_q[j] = (qv > 0.f) ? qv : (__expf(qv) - 1.f);
        }
        __syncthreads();

        // ---- Stage F: broadcast outputs ----
        float4* oe4 = (float4*)(out_elu + (size_t)pair * 4096 + vb * 2048);
        float4* oa4 = (float4*)(out_att + (size_t)pair * 4096 + vb * 2048);
        const float4* Q4 = (const float4*)s_q;
        const float4* A4 = (const float4*)s_att;
#pragma unroll
        for (int i = 0; i < 2; i++) {
            const int idx4 = t + i * 256;
            const int w4 = idx4 & 15;
            oe4[idx4] = Q4[w4];
            if (write_att) oa4[idx4] = A4[w4 & 7];
        }
    }
}

extern "C" void kernel_launch(void* const* d_in, const int* in_sizes, int n_in,
                              void* d_out, int out_size)
{
    const float* inp = (const float*)d_in[0];   // [16,12,64,64]
    // d_in[1] = adj — dead in the reference
    const float* W   = (const float*)d_in[2];   // [64,64]
    const float* a   = (const float*)d_in[3];   // [128,1]
    float* out = (float*)d_out;

    const int elu_elems = NB * TT * 64 * 64;    // 786432
    const int write_att = (out_size >= 2 * elu_elems) ? 1 : 0;
    float* out_att = out + elu_elems;

    gat_one<<<NB * TT * 2, 256>>>(inp, W, a, out, out_att, write_att);
}

// round 8
// speedup vs baseline: 1.2119x; 1.2119x over previous
#include <cuda_runtime.h>
#include <math.h>

#define NB 16
#define TT 12
#define AL 0.2f

// Dynamic smem (floats): s_W[4096] | s_src[4096]
#define DYN_BYTES ((4096 + 4096) * 4)

__global__ __launch_bounds__(256) void gat_one(
    const float* __restrict__ inp,   // [NB,TT,64,64]
    const float* __restrict__ W,     // [64,64]
    const float* __restrict__ a,     // [128]
    float* __restrict__ out_elu,     // [NB,TT,64,64]
    float* __restrict__ out_att,     // [NB,TT,64,64]
    int write_att)
{
    extern __shared__ float sm[];
    float* s_W   = sm;            // 64x64
    float* s_src = sm + 4096;     // source slab (64x64)

    __shared__ __align__(16) float s_a [128];
    __shared__ __align__(16) float s_WA[128];   // ti<6: WA1[64]; ti>=6: WAlo|WAhi
    __shared__ __align__(16) float s_cs[128];   // ti<6 own half colsums
    __shared__ __align__(16) float s_g [128];   // ti<6: g1[64]; ti>=6: g2a|g2b
    __shared__ __align__(16) float s_SW[128];   // ti<6: SW_lo|SW_hi
    __shared__ __align__(16) float s_p0[32], s_p1[32];
    __shared__ __align__(16) float s_att[32];
    __shared__ __align__(16) float s_wc[64], s_q[64];

    const int t   = threadIdx.x;
    const int bid = blockIdx.x, pair = bid >> 1, vb = bid & 1;
    const int n = pair / TT, ti = pair - n * TT;
    const bool first = (ti < 6);
    const int sl = first ? (2 * ti + vb) : (2 * (ti - 6) + vb);
    const float* src = inp + (size_t)(n * TT + sl) * 4096;
    const float* own = inp + (size_t)pair * 4096;

    // ---- Stage A: stage W + src slab; (ti<6) own half colsums direct from global ----
    {
        const float4* Wg = (const float4*)W;
        const float4* Sg = (const float4*)src;
        float4* Ws = (float4*)s_W;
        float4* Ss = (float4*)s_src;
#pragma unroll
        for (int i = 0; i < 4; i++) {
            Ws[t + i * 256] = Wg[t + i * 256];
            Ss[t + i * 256] = Sg[t + i * 256];
        }
        if (t < 128) s_a[t] = a[t];
        if (first && t >= 128) {
            const int d = t - 128;                    // 0..127
            const int hb = d >> 6, k = d & 63;
            const float* p = own + hb * 2048 + k;
            float c0 = 0.f, c1 = 0.f, c2 = 0.f, c3 = 0.f;
#pragma unroll
            for (int w = 0; w < 32; w += 4) {
                c0 += p[w * 64];
                c1 += p[(w + 1) * 64];
                c2 += p[(w + 2) * 64];
                c3 += p[(w + 3) * 64];
            }
            s_cs[d] = (c0 + c1) + (c2 + c3);
        }
    }
    __syncthreads();

    // ---- Stage B: WA matvec(s) ----
    if (first) {
        if (t < 64) {
            const int k = t;
            float s0 = 0.f, s1 = 0.f;
#pragma unroll
            for (int j0 = 0; j0 < 64; j0 += 2) {
                const int ja = (j0 + k) & 63, jb = (j0 + 1 + k) & 63;
                s0 = fmaf(s_W[k * 64 + ja], s_a[ja] + s_a[64 + ja], s0);
                s1 = fmaf(s_W[k * 64 + jb], s_a[jb] + s_a[64 + jb], s1);
            }
            s_WA[k] = s0 + s1;                       // W @ (a_lo + a_hi)
        } else if (t >= 128) {                       // SW_c[j] = cs_c . W[:,j]
            const int d = t - 128, c = d >> 6, j = d & 63;
            const float* cs = s_cs + c * 64;
            float s0 = 0.f, s1 = 0.f;
#pragma unroll
            for (int k = 0; k < 64; k += 2) {
                s0 = fmaf(cs[k],     s_W[k * 64 + j],       s0);
                s1 = fmaf(cs[k + 1], s_W[(k + 1) * 64 + j], s1);
            }
            s_SW[c * 64 + j] = s0 + s1;              // SW_lo | SW_hi
        }
    } else {
        if (t < 128) {
            const int c = t >> 6, k = t & 63;
            const float* av = s_a + c * 64;
            float s0 = 0.f, s1 = 0.f;
#pragma unroll
            for (int j0 = 0; j0 < 64; j0 += 2) {
                const int ja = (j0 + k) & 63, jb = (j0 + 1 + k) & 63;
                s0 = fmaf(s_W[k * 64 + ja], av[ja], s0);
                s1 = fmaf(s_W[k * 64 + jb], av[jb], s1);
            }
            s_WA[c * 64 + k] = s0 + s1;              // W@a_lo | W@a_hi
        }
    }
    __syncthreads();

    // ---- Stage C: g dots over the 64 src rows ----
    if (first) {
        if (t < 64) {
            const int u = t;
            float s0 = 0.f, s1 = 0.f;
#pragma unroll
            for (int k0 = 0; k0 < 64; k0 += 2) {
                const int ka = (k0 + u) & 63, kb = (k0 + 1 + u) & 63;
                s0 = fmaf(s_src[u * 64 + ka], s_WA[ka], s0);
                s1 = fmaf(s_src[u * 64 + kb], s_WA[kb], s1);
            }
            s_g[u] = s0 + s1;                        // g1[u]
        }
    } else {
        if (t < 128) {
            const int c = t >> 6, u = t & 63;
            const float* wav = s_WA + c * 64;
            float s0 = 0.f, s1 = 0.f;
#pragma unroll
            for (int k0 = 0; k0 < 64; k0 += 2) {
                const int ka = (k0 + u) & 63, kb = (k0 + 1 + u) & 63;
                s0 = fmaf(s_src[u * 64 + ka], wav[ka], s0);
                s1 = fmaf(s_src[u * 64 + kb], wav[kb], s1);
            }
            s_g[c * 64 + u] = s0 + s1;               // g2a[u] | g2b[u]
        }
    }
    __syncthreads();

    if (first) {
        // ---- Stage D: closed-form softmax ----
        if (t < 32) {
            float e0 = s_g[2 * t], e1 = s_g[2 * t + 1];
            e0 = (e0 > 0.f) ? e0 : AL * e0;
            e1 = (e1 > 0.f) ? e1 : AL * e1;
            const float m = fmaxf(e0, e1);
            const float p0 = __expf(e0 - m), p1 = __expf(e1 - m);
            const float inv = __frcp_rn(32.f * (p0 + p1));
            s_p0[t] = p0 * inv;
            s_p1[t] = p1 * inv;
        }
        __syncthreads();

        // ---- Stage E: outputs (32 rows x 64 cols) ----
        float4* oe4 = (float4*)(out_elu + (size_t)pair * 4096 + vb * 2048);
        float4* oa4 = (float4*)(out_att + (size_t)pair * 4096 + vb * 2048);
        const float4* Qlo = (const float4*)s_SW;
        const float4* Qhi = (const float4*)(s_SW + 64);
#pragma unroll
        for (int i = 0; i < 2; i++) {
            const int idx4 = t + i * 256;            // [0,512)
            const int r = idx4 >> 4, w4 = idx4 & 15;
            const float a0 = s_p0[r], a1 = s_p1[r];
            const float4 q0 = Qlo[w4], q1 = Qhi[w4];
            float4 rr;
            rr.x = fmaf(a0, q0.x, a1 * q1.x);
            rr.y = fmaf(a0, q0.y, a1 * q1.y);
            rr.z = fmaf(a0, q0.z, a1 * q1.z);
            rr.w = fmaf(a0, q0.w, a1 * q1.w);
            rr.x = (rr.x > 0.f) ? rr.x : (__expf(rr.x) - 1.f);
            rr.y = (rr.y > 0.f) ? rr.y : (__expf(rr.y) - 1.f);
            rr.z = (rr.z > 0.f) ? rr.z : (__expf(rr.z) - 1.f);
            rr.w = (rr.w > 0.f) ? rr.w : (__expf(rr.w) - 1.f);
            oe4[idx4] = rr;
            if (write_att) {
                const float av = (w4 < 8) ? a0 : a1;
                oa4[idx4] = make_float4(av, av, av, av);
            }
        }
    } else {
        // ---- Stage D: 32-wide softmax (warp 0) ----
        if (t < 32) {
            float e = s_g[2 * t] + s_g[64 + 2 * t + 1];  // g2a[2w'] + g2b[2w'+1]
            e = (e > 0.f) ? e : AL * e;
            float m = e;
#pragma unroll
            for (int o = 16; o; o >>= 1) m = fmaxf(m, __shfl_xor_sync(0xffffffffu, m, o));
            const float p = __expf(e - m);
            float ss = p;
#pragma unroll
            for (int o = 16; o; o >>= 1) ss += __shfl_xor_sync(0xffffffffu, ss, o);
            s_att[t] = p * __frcp_rn(2.f * ss);
        }
        __syncthreads();

        // ---- Stage E: weighted colsum of own slab, direct from global ----
        if (t < 64) {
            const int k = t;
            const float* p = own + k;
            float s0 = 0.f, s1 = 0.f, s2 = 0.f, s3 = 0.f;
#pragma unroll
            for (int w = 0; w < 32; w += 2) {
                s0 = fmaf(s_att[w],     p[w * 64],         s0);
                s1 = fmaf(s_att[w + 1], p[(w + 1) * 64],   s1);
                s2 = fmaf(s_att[w],     p[(w + 32) * 64],  s2);
                s3 = fmaf(s_att[w + 1], p[(w + 33) * 64],  s3);
            }
            s_wc[k] = (s0 + s1) + (s2 + s3);
        }
        __syncthreads();

        // ---- Stage F: q[j] = wc . W[:,j], fold ELU ----
        if (t < 64) {
            const int j = t;
            float s0 = 0.f, s1 = 0.f;
#pragma unroll
            for (int k = 0; k < 64; k += 2) {
                s0 = fmaf(s_wc[k],     s_W[k * 64 + j],       s0);
                s1 = fmaf(s_wc[k + 1], s_W[(k + 1) * 64 + j], s1);
            }
            const float qv = s0 + s1;
            s_q[j] = (qv > 0.f) ? qv : (__expf(qv) - 1.f);
        }
        __syncthreads();

        // ---- Stage G: broadcast outputs ----
        float4* oe4 = (float4*)(out_elu + (size_t)pair * 4096 + vb * 2048);
        float4* oa4 = (float4*)(out_att + (size_t)pair * 4096 + vb * 2048);
        const float4* Q4 = (const float4*)s_q;
        const float4* A4 = (const float4*)s_att;
#pragma unroll
        for (int i = 0; i < 2; i++) {
            const int idx4 = t + i * 256;
            const int w4 = idx4 & 15;
            oe4[idx4] = Q4[w4];
            if (write_att) oa4[idx4] = A4[w4 & 7];
        }
    }
}

extern "C" void kernel_launch(void* const* d_in, const int* in_sizes, int n_in,
                              void* d_out, int out_size)
{
    const float* inp = (const float*)d_in[0];   // [16,12,64,64]
    // d_in[1] = adj — dead in the reference
    const float* W   = (const float*)d_in[2];   // [64,64]
    const float* a   = (const float*)d_in[3];   // [128,1]
    float* out = (float*)d_out;

    const int elu_elems = NB * TT * 64 * 64;    // 786432
    const int write_att = (out_size >= 2 * elu_elems) ? 1 : 0;
    float* out_att = out + elu_elems;

    gat_one<<<NB * TT * 2, 256, DYN_BYTES>>>(inp, W, a, out, out_att, write_att);
}